// round 5
// baseline (speedup 1.0000x reference)
#include <cuda_runtime.h>
#include <cuda_bf16.h>
#include <math.h>
#include <stdint.h>

#define T_TOK 2048
#define Dm    512
#define Hm    1024
#define Em    8
#define CAP   2048

// ---------------- scratch (static device globals) ----------------
__device__ int   g_count[Em];
__device__ int   g_list[Em * CAP];
__device__ float g_wt[2 * T_TOK];

__device__ __align__(16) __nv_bfloat16 g_w1hi[Em * Hm * Dm];
__device__ __align__(16) __nv_bfloat16 g_w1lo[Em * Hm * Dm];
__device__ __align__(16) __nv_bfloat16 g_w2hi[Em * Dm * Hm];
__device__ __align__(16) __nv_bfloat16 g_w2lo[Em * Dm * Hm];
__device__ __align__(16) __nv_bfloat16 g_xhi[Em * CAP * Dm];
__device__ __align__(16) __nv_bfloat16 g_xlo[Em * CAP * Dm];
__device__ __align__(16) __nv_bfloat16 g_hhi[Em * CAP * Hm];
__device__ __align__(16) __nv_bfloat16 g_hlo[Em * CAP * Hm];

// ---------------- PTX helpers ----------------
__device__ __forceinline__ uint32_t smem_u32(const void* p) {
    uint32_t a;
    asm("{ .reg .u64 t; cvta.to.shared.u64 t, %1; cvt.u32.u64 %0, t; }" : "=r"(a) : "l"(p));
    return a;
}
__device__ __forceinline__ void cp16(uint32_t dst, const void* src) {
    asm volatile("cp.async.cg.shared.global [%0], [%1], 16;" :: "r"(dst), "l"(src));
}
#define CP_COMMIT() asm volatile("cp.async.commit_group;" ::: "memory")
#define CP_WAIT(n)  asm volatile("cp.async.wait_group %0;" :: "n"(n) : "memory")

__device__ __forceinline__ uint32_t swz(uint32_t off) { return off ^ ((off >> 3) & 0x70); }

__device__ __forceinline__ void ldm_x4(uint32_t* r, uint32_t addr) {
    asm volatile("ldmatrix.sync.aligned.m8n8.x4.shared.b16 {%0,%1,%2,%3}, [%4];"
                 : "=r"(r[0]), "=r"(r[1]), "=r"(r[2]), "=r"(r[3]) : "r"(addr));
}
__device__ __forceinline__ void mma16816(float* c, const uint32_t* a, uint32_t b0, uint32_t b1) {
    asm volatile("mma.sync.aligned.m16n8k16.row.col.f32.bf16.bf16.f32 "
                 "{%0,%1,%2,%3}, {%4,%5,%6,%7}, {%8,%9}, {%0,%1,%2,%3};"
                 : "+f"(c[0]), "+f"(c[1]), "+f"(c[2]), "+f"(c[3])
                 : "r"(a[0]), "r"(a[1]), "r"(a[2]), "r"(a[3]), "r"(b0), "r"(b1));
}

__device__ __forceinline__ void stage_tile(uint32_t sbase, const __nv_bfloat16* src,
                                           int stride, int tid) {
    for (int q = tid; q < 1024; q += 256) {
        int r = q >> 3, c = q & 7;
        cp16(sbase + swz((uint32_t)(r * 128 + c * 16)), src + (size_t)r * stride + c * 8);
    }
}

// ---------------- zero: out buffer + counts ----------------
__global__ void zero_kernel(float* __restrict__ out) {
    int i = blockIdx.x * 256 + threadIdx.x;
    ((float4*)out)[i] = make_float4(0.f, 0.f, 0.f, 0.f);
    if (blockIdx.x == 0 && threadIdx.x < Em) g_count[threadIdx.x] = 0;
}

__device__ __forceinline__ void split8(const float* f, __nv_bfloat16* h, __nv_bfloat16* l) {
#pragma unroll
    for (int j = 0; j < 8; j++) {
        __nv_bfloat16 hh = __float2bfloat16_rn(f[j]);
        h[j] = hh;
        l[j] = __float2bfloat16_rn(f[j] - __bfloat162float(hh));
    }
}

__global__ void convertw1_kernel(const float* __restrict__ src) {
    int i = blockIdx.x * 256 + threadIdx.x;
    const float4* s = (const float4*)src + (size_t)i * 2;
    float4 a = s[0], b = s[1];
    float f[8] = {a.x, a.y, a.z, a.w, b.x, b.y, b.z, b.w};
    alignas(16) __nv_bfloat16 h[8], l[8];
    split8(f, h, l);
    *(uint4*)(g_w1hi + (size_t)i * 8) = *(uint4*)h;
    *(uint4*)(g_w1lo + (size_t)i * 8) = *(uint4*)l;
}
__global__ void convertw2_kernel(const float* __restrict__ src) {
    int i = blockIdx.x * 256 + threadIdx.x;
    const float4* s = (const float4*)src + (size_t)i * 2;
    float4 a = s[0], b = s[1];
    float f[8] = {a.x, a.y, a.z, a.w, b.x, b.y, b.z, b.w};
    alignas(16) __nv_bfloat16 h[8], l[8];
    split8(f, h, l);
    *(uint4*)(g_w2hi + (size_t)i * 8) = *(uint4*)h;
    *(uint4*)(g_w2lo + (size_t)i * 8) = *(uint4*)l;
}

// ---------------- router + fused gather (block = 2 warps for even SM spread) ----------------
__global__ __launch_bounds__(64) void router_kernel(const float* __restrict__ x,
                                                    const float* __restrict__ wr,
                                                    const float* __restrict__ br,
                                                    float* __restrict__ logits_out) {
    const int warp = threadIdx.x >> 5;
    const int lane = threadIdx.x & 31;
    const int t = blockIdx.x * 2 + warp;

    const float4* xv4 = (const float4*)(x) + (size_t)t * (Dm / 4);
    float4 xv[4];
#pragma unroll
    for (int i = 0; i < 4; i++) xv[i] = xv4[i * 32 + lane];

    float acc[Em];
#pragma unroll
    for (int e = 0; e < Em; e++) {
        const float4* wv4 = (const float4*)(wr) + (size_t)e * (Dm / 4);
        float a = 0.f;
#pragma unroll
        for (int i = 0; i < 4; i++) {
            float4 w = wv4[i * 32 + lane];
            a += xv[i].x * w.x + xv[i].y * w.y + xv[i].z * w.z + xv[i].w * w.w;
        }
        acc[e] = a;
    }
#pragma unroll
    for (int off = 16; off > 0; off >>= 1)
#pragma unroll
        for (int e = 0; e < Em; e++)
            acc[e] += __shfl_xor_sync(0xffffffffu, acc[e], off);
#pragma unroll
    for (int e = 0; e < Em; e++) acc[e] += br[e];

    int pack0 = 0, pack1 = 0;
    if (lane == 0) {
        *(float4*)(logits_out + (size_t)t * Em)     = make_float4(acc[0], acc[1], acc[2], acc[3]);
        *(float4*)(logits_out + (size_t)t * Em + 4) = make_float4(acc[4], acc[5], acc[6], acc[7]);
        float mx = acc[0];
#pragma unroll
        for (int e = 1; e < Em; e++) mx = fmaxf(mx, acc[e]);
        float p[Em]; float s = 0.f;
#pragma unroll
        for (int e = 0; e < Em; e++) { p[e] = expf(acc[e] - mx); s += p[e]; }
        float inv = 1.0f / s;
#pragma unroll
        for (int e = 0; e < Em; e++) p[e] *= inv;
        int e0 = 0;
#pragma unroll
        for (int e = 1; e < Em; e++) if (p[e] > p[e0]) e0 = e;
        int e1 = (e0 == 0) ? 1 : 0;
#pragma unroll
        for (int e = 0; e < Em; e++) if (e != e0 && p[e] > p[e1]) e1 = e;
        float sum2 = p[e0] + p[e1];
        g_wt[2 * t + 0] = p[e0] / sum2;
        g_wt[2 * t + 1] = p[e1] / sum2;
        int pos0 = atomicAdd(&g_count[e0], 1);
        g_list[e0 * CAP + pos0] = 2 * t + 0;
        int pos1 = atomicAdd(&g_count[e1], 1);
        g_list[e1 * CAP + pos1] = 2 * t + 1;
        pack0 = (e0 << 16) | pos0;
        pack1 = (e1 << 16) | pos1;
    }
    pack0 = __shfl_sync(0xffffffffu, pack0, 0);
    pack1 = __shfl_sync(0xffffffffu, pack1, 0);
    const int e0 = pack0 >> 16, pos0 = pack0 & 0xffff;
    const int e1 = pack1 >> 16, pos1 = pack1 & 0xffff;

    __nv_bfloat16* dh0 = g_xhi + ((size_t)e0 * CAP + pos0) * Dm;
    __nv_bfloat16* dl0 = g_xlo + ((size_t)e0 * CAP + pos0) * Dm;
    __nv_bfloat16* dh1 = g_xhi + ((size_t)e1 * CAP + pos1) * Dm;
    __nv_bfloat16* dl1 = g_xlo + ((size_t)e1 * CAP + pos1) * Dm;
#pragma unroll
    for (int i = 0; i < 4; i++) {
        float f[4] = {xv[i].x, xv[i].y, xv[i].z, xv[i].w};
        alignas(8) __nv_bfloat16 h[4], l[4];
#pragma unroll
        for (int j = 0; j < 4; j++) {
            __nv_bfloat16 hh = __float2bfloat16_rn(f[j]);
            h[j] = hh;
            l[j] = __float2bfloat16_rn(f[j] - __bfloat162float(hh));
        }
        int eo = (i * 32 + lane) * 4;
        *(uint2*)(dh0 + eo) = *(uint2*)h;
        *(uint2*)(dl0 + eo) = *(uint2*)l;
        *(uint2*)(dh1 + eo) = *(uint2*)h;
        *(uint2*)(dl1 + eo) = *(uint2*)l;
    }
}

// ---------------- warp-MMA GEMM mainloop: 3-stage, 1 sync/iter ----------------
extern __shared__ char smx[];

#define STAGE_J(j, bufi)                                                              \
    do {                                                                              \
        const int seg_ = (j) >> SEG_SHIFT, kt_ = (j) & SEG_MASK;                      \
        uint32_t sb2_ = smb + (bufi) * 32768;                                         \
        stage_tile(sb2_,         Aseg[seg_] + aoff + kt_ * 64, STRIDE, tid);          \
        stage_tile(sb2_ + 16384, Bseg[seg_] + boff + kt_ * 64, STRIDE, tid);          \
        CP_COMMIT();                                                                  \
    } while (0)

#define GEMM_MAINLOOP(NT, SEG_SHIFT_V, SEG_MASK_V, STRIDE_V)                          \
    enum { SEG_SHIFT = SEG_SHIFT_V, SEG_MASK = SEG_MASK_V, STRIDE = STRIDE_V };       \
    uint32_t smb = smem_u32(smx);                                                     \
    STAGE_J(0, 0);                                                                    \
    STAGE_J(1, 1);                                                                    \
    float acc[4][4][4];                                                               \
    _Pragma("unroll") for (int a1 = 0; a1 < 4; a1++)                                  \
    _Pragma("unroll") for (int a2 = 0; a2 < 4; a2++)                                  \
    _Pragma("unroll") for (int a3 = 0; a3 < 4; a3++) acc[a1][a2][a3] = 0.f;           \
    const int lr = lane & 15, lc = lane >> 4;                                         \
    int bc = 0, bs = 2;                                                               \
    for (int i = 0; i < NT; i++) {                                                    \
        if (i < NT - 1) CP_WAIT(1); else CP_WAIT(0);                                  \
        __syncthreads();                                                              \
        if (i + 2 < NT) { STAGE_J(i + 2, bs); bs = (bs == 2) ? 0 : bs + 1; }          \
        uint32_t sa = smb + bc * 32768, sbb = sa + 16384;                             \
        bc = (bc == 2) ? 0 : bc + 1;                                                  \
        _Pragma("unroll")                                                             \
        for (int kk = 0; kk < 64; kk += 16) {                                         \
            uint32_t af[4][4];                                                        \
            _Pragma("unroll")                                                         \
            for (int mi = 0; mi < 4; mi++) {                                          \
                uint32_t off = (uint32_t)((warpM * 64 + mi * 16 + lr) * 128           \
                                          + (kk / 8 + lc) * 16);                      \
                ldm_x4(af[mi], sa + swz(off));                                        \
            }                                                                         \
            uint32_t bfr[2][4];                                                       \
            _Pragma("unroll")                                                         \
            for (int nj = 0; nj < 2; nj++) {                                          \
                uint32_t off = (uint32_t)((warpN * 32 + nj * 16 + lr) * 128           \
                                          + (kk / 8 + lc) * 16);                      \
                ldm_x4(bfr[nj], sbb + swz(off));                                      \
            }                                                                         \
            _Pragma("unroll")                                                         \
            for (int mi = 0; mi < 4; mi++)                                            \
                _Pragma("unroll")                                                     \
                for (int ni = 0; ni < 4; ni++) {                                      \
                    const int nj = ni >> 1, sub = ni & 1;                             \
                    mma16816(acc[mi][ni], af[mi], bfr[nj][sub], bfr[nj][sub + 2]);    \
                }                                                                     \
        }                                                                             \
    }

// ---------------- fc1: h = gelu(X @ W1^T) ----------------
__global__ __launch_bounds__(256, 2) void fc1_kernel() {
    const int e = blockIdx.z;
    const int cnt = g_count[e];
    const int rowbase = blockIdx.y * 128;
    if (rowbase >= cnt) return;
    const int nbase = blockIdx.x * 128;

    const int tid = threadIdx.x;
    const int wid = tid >> 5, lane = tid & 31;
    const int warpM = wid >> 2, warpN = wid & 3;

    const __nv_bfloat16* Aseg[3] = {g_xhi, g_xhi, g_xlo};
    const __nv_bfloat16* Bseg[3] = {g_w1hi, g_w1lo, g_w1hi};
    const size_t aoff = ((size_t)e * CAP + rowbase) * Dm;
    const size_t boff = ((size_t)e * Hm + nbase) * Dm;

    GEMM_MAINLOOP(24, 3, 7, Dm)

    const int r0 = lane >> 2, c0 = (lane & 3) * 2;
#pragma unroll
    for (int mi = 0; mi < 4; mi++) {
#pragma unroll
        for (int half = 0; half < 2; half++) {
            int row = rowbase + warpM * 64 + mi * 16 + r0 + half * 8;
            size_t rg = ((size_t)e * CAP + row) * Hm + nbase + warpN * 32 + c0;
#pragma unroll
            for (int ni = 0; ni < 4; ni++) {
                float v0 = acc[mi][ni][half * 2 + 0];
                float v1 = acc[mi][ni][half * 2 + 1];
                float gg0 = 0.5f * v0 * (1.0f + erff(v0 * 0.70710678118654752f));
                float gg1 = 0.5f * v1 * (1.0f + erff(v1 * 0.70710678118654752f));
                __nv_bfloat16 h0 = __float2bfloat16_rn(gg0);
                __nv_bfloat16 h1 = __float2bfloat16_rn(gg1);
                __nv_bfloat16 l0 = __float2bfloat16_rn(gg0 - __bfloat162float(h0));
                __nv_bfloat16 l1 = __float2bfloat16_rn(gg1 - __bfloat162float(h1));
                uint32_t hp = (uint32_t)*(uint16_t*)&h0 | ((uint32_t)*(uint16_t*)&h1 << 16);
                uint32_t lp = (uint32_t)*(uint16_t*)&l0 | ((uint32_t)*(uint16_t*)&l1 << 16);
                *(uint32_t*)(g_hhi + rg + ni * 8) = hp;
                *(uint32_t*)(g_hlo + rg + ni * 8) = lp;
            }
        }
    }
}

// ---------------- fc2: out[tok] += w * (H @ W2^T)  (atomic combine) ----------------
__global__ __launch_bounds__(256, 2) void fc2_kernel(float* __restrict__ out) {
    const int e = blockIdx.z;
    const int cnt = g_count[e];
    const int rowbase = blockIdx.y * 128;
    if (rowbase >= cnt) return;
    const int nbase = blockIdx.x * 128;

    const int tid = threadIdx.x;
    const int wid = tid >> 5, lane = tid & 31;
    const int warpM = wid >> 2, warpN = wid & 3;

    const __nv_bfloat16* Aseg[3] = {g_hhi, g_hhi, g_hlo};
    const __nv_bfloat16* Bseg[3] = {g_w2hi, g_w2lo, g_w2hi};
    const size_t aoff = ((size_t)e * CAP + rowbase) * Hm;
    const size_t boff = ((size_t)e * Dm + nbase) * Hm;

    GEMM_MAINLOOP(48, 4, 15, Hm)

    const int r0 = lane >> 2, c0 = (lane & 3) * 2;
#pragma unroll
    for (int mi = 0; mi < 4; mi++) {
#pragma unroll
        for (int half = 0; half < 2; half++) {
            int pos = rowbase + warpM * 64 + mi * 16 + r0 + half * 8;
            if (pos >= cnt) continue;
            int entry = g_list[e * CAP + pos];
            float w = g_wt[entry];
            int tok = entry >> 1;
            float* op = out + (size_t)tok * Dm + nbase + warpN * 32 + c0;
#pragma unroll
            for (int ni = 0; ni < 4; ni++) {
                atomicAdd(op + ni * 8,     w * acc[mi][ni][half * 2 + 0]);
                atomicAdd(op + ni * 8 + 1, w * acc[mi][ni][half * 2 + 1]);
            }
        }
    }
}

// ---------------- launch ----------------
extern "C" void kernel_launch(void* const* d_in, const int* in_sizes, int n_in,
                              void* d_out, int out_size) {
    const float* x  = (const float*)d_in[0];
    const float* wr = (const float*)d_in[1];
    const float* br = (const float*)d_in[2];
    const float* w1 = (const float*)d_in[3];
    const float* w2 = (const float*)d_in[4];
    float* out = (float*)d_out;
    float* logits = out + (size_t)T_TOK * Dm;

    static int attr_done = 0;
    if (!attr_done) {
        cudaFuncSetAttribute(fc1_kernel, cudaFuncAttributeMaxDynamicSharedMemorySize, 98304);
        cudaFuncSetAttribute(fc2_kernel, cudaFuncAttributeMaxDynamicSharedMemorySize, 98304);
        attr_done = 1;
    }

    int n8 = (Em * Hm * Dm) / 8;
    zero_kernel<<<(T_TOK * Dm / 4) / 256, 256>>>(out);       // 1
    convertw1_kernel<<<n8 / 256, 256>>>(w1);                 // 2
    router_kernel<<<T_TOK / 2, 64>>>(x, wr, br, logits);     // 3
    dim3 g1(Hm / 128, CAP / 128, Em);
    fc1_kernel<<<g1, 256, 98304>>>();                        // 4  <-- profiled slot
    convertw2_kernel<<<n8 / 256, 256>>>(w2);                 // 5
    dim3 g2(Dm / 128, CAP / 128, Em);
    fc2_kernel<<<g2, 256, 98304>>>(out);                     // 6
}

// round 6
// speedup vs baseline: 1.0892x; 1.0892x over previous
#include <cuda_runtime.h>
#include <cuda_bf16.h>
#include <math.h>
#include <stdint.h>

#define T_TOK 2048
#define Dm    512
#define Hm    1024
#define Em    8
#define CAP   2048

// ---------------- scratch (static device globals) ----------------
__device__ int   g_count[Em];
__device__ int   g_list[Em * CAP];
__device__ float g_wt[2 * T_TOK];

__device__ __align__(16) __nv_bfloat16 g_w1hi[Em * Hm * Dm];
__device__ __align__(16) __nv_bfloat16 g_w1lo[Em * Hm * Dm];
__device__ __align__(16) __nv_bfloat16 g_w2hi[Em * Dm * Hm];
__device__ __align__(16) __nv_bfloat16 g_w2lo[Em * Dm * Hm];
__device__ __align__(16) __nv_bfloat16 g_xhi[Em * CAP * Dm];
__device__ __align__(16) __nv_bfloat16 g_xlo[Em * CAP * Dm];
__device__ __align__(16) __nv_bfloat16 g_hhi[Em * CAP * Hm];
__device__ __align__(16) __nv_bfloat16 g_hlo[Em * CAP * Hm];

// ---------------- PTX helpers ----------------
__device__ __forceinline__ uint32_t smem_u32(const void* p) {
    uint32_t a;
    asm("{ .reg .u64 t; cvta.to.shared.u64 t, %1; cvt.u32.u64 %0, t; }" : "=r"(a) : "l"(p));
    return a;
}
__device__ __forceinline__ void cp16(uint32_t dst, const void* src) {
    asm volatile("cp.async.cg.shared.global [%0], [%1], 16;" :: "r"(dst), "l"(src));
}
#define CP_COMMIT() asm volatile("cp.async.commit_group;" ::: "memory")
#define CP_WAIT(n)  asm volatile("cp.async.wait_group %0;" :: "n"(n) : "memory")

__device__ __forceinline__ uint32_t swz(uint32_t off) { return off ^ ((off >> 3) & 0x70); }

__device__ __forceinline__ void ldm_x4(uint32_t* r, uint32_t addr) {
    asm volatile("ldmatrix.sync.aligned.m8n8.x4.shared.b16 {%0,%1,%2,%3}, [%4];"
                 : "=r"(r[0]), "=r"(r[1]), "=r"(r[2]), "=r"(r[3]) : "r"(addr));
}
__device__ __forceinline__ void mma16816(float* c, const uint32_t* a, uint32_t b0, uint32_t b1) {
    asm volatile("mma.sync.aligned.m16n8k16.row.col.f32.bf16.bf16.f32 "
                 "{%0,%1,%2,%3}, {%4,%5,%6,%7}, {%8,%9}, {%0,%1,%2,%3};"
                 : "+f"(c[0]), "+f"(c[1]), "+f"(c[2]), "+f"(c[3])
                 : "r"(a[0]), "r"(a[1]), "r"(a[2]), "r"(a[3]), "r"(b0), "r"(b1));
}

__device__ __forceinline__ void stage_tile(uint32_t sbase, const __nv_bfloat16* src,
                                           int stride, int tid) {
#pragma unroll
    for (int q4 = 0; q4 < 4; q4++) {
        int q = tid + q4 * 256;
        int r = q >> 3, c = q & 7;
        cp16(sbase + swz((uint32_t)(r * 128 + c * 16)), src + (size_t)r * stride + c * 8);
    }
}

// ---------------- prep: zero out/counts + both weight splits (one kernel) ----------------
__device__ __forceinline__ void split8(const float* f, __nv_bfloat16* h, __nv_bfloat16* l) {
#pragma unroll
    for (int j = 0; j < 8; j++) {
        __nv_bfloat16 hh = __float2bfloat16_rn(f[j]);
        h[j] = hh;
        l[j] = __float2bfloat16_rn(f[j] - __bfloat162float(hh));
    }
}
__device__ __forceinline__ void conv_one(const float* src, __nv_bfloat16* hi,
                                         __nv_bfloat16* lo, int i) {
    const float4* s = (const float4*)src + (size_t)i * 2;
    float4 a = s[0], b = s[1];
    float f[8] = {a.x, a.y, a.z, a.w, b.x, b.y, b.z, b.w};
    alignas(16) __nv_bfloat16 h[8], l[8];
    split8(f, h, l);
    *(uint4*)(hi + (size_t)i * 8) = *(uint4*)h;
    *(uint4*)(lo + (size_t)i * 8) = *(uint4*)l;
}

// blocks: [0,1024) zero out; [1024,3072) w1; [3072,5120) w2
__global__ void prep_kernel(float* __restrict__ out,
                            const float* __restrict__ w1,
                            const float* __restrict__ w2) {
    int b = blockIdx.x;
    if (b < 1024) {
        ((float4*)out)[b * 256 + threadIdx.x] = make_float4(0.f, 0.f, 0.f, 0.f);
        if (b == 0 && threadIdx.x < Em) g_count[threadIdx.x] = 0;
    } else if (b < 3072) {
        conv_one(w1, g_w1hi, g_w1lo, (b - 1024) * 256 + threadIdx.x);
    } else {
        conv_one(w2, g_w2hi, g_w2lo, (b - 3072) * 256 + threadIdx.x);
    }
}

// ---------------- router + fused gather: 2 tokens per warp ----------------
__global__ __launch_bounds__(64) void router_kernel(const float* __restrict__ x,
                                                    const float* __restrict__ wr,
                                                    const float* __restrict__ br,
                                                    float* __restrict__ logits_out) {
    const int warp = threadIdx.x >> 5;
    const int lane = threadIdx.x & 31;
    const int t0 = (blockIdx.x * 2 + warp) * 2;

    float4 xv[2][4];
#pragma unroll
    for (int s = 0; s < 2; s++) {
        const float4* xv4 = (const float4*)(x) + (size_t)(t0 + s) * (Dm / 4);
#pragma unroll
        for (int i = 0; i < 4; i++) xv[s][i] = xv4[i * 32 + lane];
    }

    float acc[2][Em];
#pragma unroll
    for (int e = 0; e < Em; e++) {
        const float4* wv4 = (const float4*)(wr) + (size_t)e * (Dm / 4);
        float4 wv[4];
#pragma unroll
        for (int i = 0; i < 4; i++) wv[i] = wv4[i * 32 + lane];
#pragma unroll
        for (int s = 0; s < 2; s++) {
            float a = 0.f;
#pragma unroll
            for (int i = 0; i < 4; i++)
                a += xv[s][i].x * wv[i].x + xv[s][i].y * wv[i].y
                   + xv[s][i].z * wv[i].z + xv[s][i].w * wv[i].w;
            acc[s][e] = a;
        }
    }
#pragma unroll
    for (int off = 16; off > 0; off >>= 1)
#pragma unroll
        for (int s = 0; s < 2; s++)
#pragma unroll
            for (int e = 0; e < Em; e++)
                acc[s][e] += __shfl_xor_sync(0xffffffffu, acc[s][e], off);

#pragma unroll
    for (int s = 0; s < 2; s++) {
        const int t = t0 + s;
        float* lg = acc[s];
#pragma unroll
        for (int e = 0; e < Em; e++) lg[e] += br[e];

        int pack0 = 0, pack1 = 0;
        if (lane == 0) {
            *(float4*)(logits_out + (size_t)t * Em)     = make_float4(lg[0], lg[1], lg[2], lg[3]);
            *(float4*)(logits_out + (size_t)t * Em + 4) = make_float4(lg[4], lg[5], lg[6], lg[7]);
            float mx = lg[0];
#pragma unroll
            for (int e = 1; e < Em; e++) mx = fmaxf(mx, lg[e]);
            float p[Em]; float sum = 0.f;
#pragma unroll
            for (int e = 0; e < Em; e++) { p[e] = expf(lg[e] - mx); sum += p[e]; }
            float inv = 1.0f / sum;
#pragma unroll
            for (int e = 0; e < Em; e++) p[e] *= inv;
            int e0 = 0;
#pragma unroll
            for (int e = 1; e < Em; e++) if (p[e] > p[e0]) e0 = e;
            int e1 = (e0 == 0) ? 1 : 0;
#pragma unroll
            for (int e = 0; e < Em; e++) if (e != e0 && p[e] > p[e1]) e1 = e;
            float sum2 = p[e0] + p[e1];
            g_wt[2 * t + 0] = p[e0] / sum2;
            g_wt[2 * t + 1] = p[e1] / sum2;
            int pos0 = atomicAdd(&g_count[e0], 1);
            g_list[e0 * CAP + pos0] = 2 * t + 0;
            int pos1 = atomicAdd(&g_count[e1], 1);
            g_list[e1 * CAP + pos1] = 2 * t + 1;
            pack0 = (e0 << 16) | pos0;
            pack1 = (e1 << 16) | pos1;
        }
        pack0 = __shfl_sync(0xffffffffu, pack0, 0);
        pack1 = __shfl_sync(0xffffffffu, pack1, 0);
        const int e0 = pack0 >> 16, pos0 = pack0 & 0xffff;
        const int e1 = pack1 >> 16, pos1 = pack1 & 0xffff;

        __nv_bfloat16* dh0 = g_xhi + ((size_t)e0 * CAP + pos0) * Dm;
        __nv_bfloat16* dl0 = g_xlo + ((size_t)e0 * CAP + pos0) * Dm;
        __nv_bfloat16* dh1 = g_xhi + ((size_t)e1 * CAP + pos1) * Dm;
        __nv_bfloat16* dl1 = g_xlo + ((size_t)e1 * CAP + pos1) * Dm;
#pragma unroll
        for (int i = 0; i < 4; i++) {
            float f[4] = {xv[s][i].x, xv[s][i].y, xv[s][i].z, xv[s][i].w};
            alignas(8) __nv_bfloat16 h[4], l[4];
#pragma unroll
            for (int j = 0; j < 4; j++) {
                __nv_bfloat16 hh = __float2bfloat16_rn(f[j]);
                h[j] = hh;
                l[j] = __float2bfloat16_rn(f[j] - __bfloat162float(hh));
            }
            int eo = (i * 32 + lane) * 4;
            *(uint2*)(dh0 + eo) = *(uint2*)h;
            *(uint2*)(dl0 + eo) = *(uint2*)l;
            *(uint2*)(dh1 + eo) = *(uint2*)h;
            *(uint2*)(dl1 + eo) = *(uint2*)l;
        }
    }
}

// ---------------- warp-MMA GEMM mainloop: 3-stage smem, frag double-buffer ----------------
extern __shared__ char smx[];

#define STAGE_J(j, bufi)                                                              \
    do {                                                                              \
        const int seg_ = (j) >> SEG_SHIFT, kt_ = (j) & SEG_MASK;                      \
        uint32_t sb2_ = smb + (bufi) * 32768;                                         \
        stage_tile(sb2_,         Aseg[seg_] + aoff + kt_ * 64, STRIDE, tid);          \
        stage_tile(sb2_ + 16384, Bseg[seg_] + boff + kt_ * 64, STRIDE, tid);          \
        CP_COMMIT();                                                                  \
    } while (0)

#define LOAD_FRAGS(kk16, AF, BF)                                                      \
    do {                                                                              \
        _Pragma("unroll")                                                             \
        for (int mi_ = 0; mi_ < 4; mi_++) {                                           \
            uint32_t off_ = (uint32_t)((warpM * 64 + mi_ * 16 + lr) * 128             \
                                       + ((kk16) * 2 + lc) * 16);                     \
            ldm_x4((AF)[mi_], sa + swz(off_));                                        \
        }                                                                             \
        _Pragma("unroll")                                                             \
        for (int nj_ = 0; nj_ < 2; nj_++) {                                           \
            uint32_t off_ = (uint32_t)((warpN * 32 + nj_ * 16 + lr) * 128             \
                                       + ((kk16) * 2 + lc) * 16);                     \
            ldm_x4((BF)[nj_], sbb + swz(off_));                                       \
        }                                                                             \
    } while (0)

#define MMA_BLOCK(AF, BF)                                                             \
    do {                                                                              \
        _Pragma("unroll")                                                             \
        for (int mi_ = 0; mi_ < 4; mi_++)                                             \
            _Pragma("unroll")                                                         \
            for (int ni_ = 0; ni_ < 4; ni_++) {                                       \
                const int nj_ = ni_ >> 1, sub_ = ni_ & 1;                             \
                mma16816(acc[mi_][ni_], (AF)[mi_], (BF)[nj_][sub_],                   \
                         (BF)[nj_][sub_ + 2]);                                        \
            }                                                                         \
    } while (0)

#define GEMM_MAINLOOP(NT, SEG_SHIFT_V, SEG_MASK_V, STRIDE_V)                          \
    enum { SEG_SHIFT = SEG_SHIFT_V, SEG_MASK = SEG_MASK_V, STRIDE = STRIDE_V };       \
    uint32_t smb = smem_u32(smx);                                                     \
    STAGE_J(0, 0);                                                                    \
    STAGE_J(1, 1);                                                                    \
    float acc[4][4][4];                                                               \
    _Pragma("unroll") for (int a1 = 0; a1 < 4; a1++)                                  \
    _Pragma("unroll") for (int a2 = 0; a2 < 4; a2++)                                  \
    _Pragma("unroll") for (int a3 = 0; a3 < 4; a3++) acc[a1][a2][a3] = 0.f;           \
    const int lr = lane & 15, lc = lane >> 4;                                         \
    int bc = 0, bs = 2;                                                               \
    for (int i = 0; i < NT; i++) {                                                    \
        if (i < NT - 1) CP_WAIT(1); else CP_WAIT(0);                                  \
        __syncthreads();                                                              \
        if (i + 2 < NT) { STAGE_J(i + 2, bs); bs = (bs == 2) ? 0 : bs + 1; }          \
        uint32_t sa = smb + bc * 32768, sbb = sa + 16384;                             \
        bc = (bc == 2) ? 0 : bc + 1;                                                  \
        uint32_t af[2][4][4], bfr[2][2][4];                                           \
        LOAD_FRAGS(0, af[0], bfr[0]);                                                 \
        _Pragma("unroll")                                                             \
        for (int kk16 = 0; kk16 < 4; kk16++) {                                        \
            const int cur = kk16 & 1;                                                 \
            if (kk16 < 3) LOAD_FRAGS(kk16 + 1, af[cur ^ 1], bfr[cur ^ 1]);            \
            MMA_BLOCK(af[cur], bfr[cur]);                                             \
        }                                                                             \
    }

// ---------------- fc1: h = gelu(X @ W1^T) ----------------
__global__ __launch_bounds__(256) void fc1_kernel() {
    const int e = blockIdx.z;
    const int cnt = g_count[e];
    const int rowbase = blockIdx.y * 128;
    if (rowbase >= cnt) return;
    const int nbase = blockIdx.x * 128;

    const int tid = threadIdx.x;
    const int wid = tid >> 5, lane = tid & 31;
    const int warpM = wid >> 2, warpN = wid & 3;

    const __nv_bfloat16* Aseg[3] = {g_xhi, g_xhi, g_xlo};
    const __nv_bfloat16* Bseg[3] = {g_w1hi, g_w1lo, g_w1hi};
    const size_t aoff = ((size_t)e * CAP + rowbase) * Dm;
    const size_t boff = ((size_t)e * Hm + nbase) * Dm;

    GEMM_MAINLOOP(24, 3, 7, Dm)

    const int r0 = lane >> 2, c0 = (lane & 3) * 2;
#pragma unroll
    for (int mi = 0; mi < 4; mi++) {
#pragma unroll
        for (int half = 0; half < 2; half++) {
            int row = rowbase + warpM * 64 + mi * 16 + r0 + half * 8;
            size_t rg = ((size_t)e * CAP + row) * Hm + nbase + warpN * 32 + c0;
#pragma unroll
            for (int ni = 0; ni < 4; ni++) {
                float v0 = acc[mi][ni][half * 2 + 0];
                float v1 = acc[mi][ni][half * 2 + 1];
                float gg0 = 0.5f * v0 * (1.0f + erff(v0 * 0.70710678118654752f));
                float gg1 = 0.5f * v1 * (1.0f + erff(v1 * 0.70710678118654752f));
                __nv_bfloat16 h0 = __float2bfloat16_rn(gg0);
                __nv_bfloat16 h1 = __float2bfloat16_rn(gg1);
                __nv_bfloat16 l0 = __float2bfloat16_rn(gg0 - __bfloat162float(h0));
                __nv_bfloat16 l1 = __float2bfloat16_rn(gg1 - __bfloat162float(h1));
                uint32_t hp = (uint32_t)*(uint16_t*)&h0 | ((uint32_t)*(uint16_t*)&h1 << 16);
                uint32_t lp = (uint32_t)*(uint16_t*)&l0 | ((uint32_t)*(uint16_t*)&l1 << 16);
                *(uint32_t*)(g_hhi + rg + ni * 8) = hp;
                *(uint32_t*)(g_hlo + rg + ni * 8) = lp;
            }
        }
    }
}

// ---------------- fc2: out[tok] += w * (H @ W2^T)  (atomic combine) ----------------
__global__ __launch_bounds__(256) void fc2_kernel(float* __restrict__ out) {
    const int e = blockIdx.z;
    const int cnt = g_count[e];
    const int rowbase = blockIdx.y * 128;
    if (rowbase >= cnt) return;
    const int nbase = blockIdx.x * 128;

    const int tid = threadIdx.x;
    const int wid = tid >> 5, lane = tid & 31;
    const int warpM = wid >> 2, warpN = wid & 3;

    const __nv_bfloat16* Aseg[3] = {g_hhi, g_hhi, g_hlo};
    const __nv_bfloat16* Bseg[3] = {g_w2hi, g_w2lo, g_w2hi};
    const size_t aoff = ((size_t)e * CAP + rowbase) * Hm;
    const size_t boff = ((size_t)e * Dm + nbase) * Hm;

    GEMM_MAINLOOP(48, 4, 15, Hm)

    const int r0 = lane >> 2, c0 = (lane & 3) * 2;
#pragma unroll
    for (int mi = 0; mi < 4; mi++) {
#pragma unroll
        for (int half = 0; half < 2; half++) {
            int pos = rowbase + warpM * 64 + mi * 16 + r0 + half * 8;
            if (pos >= cnt) continue;
            int entry = g_list[e * CAP + pos];
            float w = g_wt[entry];
            int tok = entry >> 1;
            float* op = out + (size_t)tok * Dm + nbase + warpN * 32 + c0;
#pragma unroll
            for (int ni = 0; ni < 4; ni++) {
                atomicAdd(op + ni * 8,     w * acc[mi][ni][half * 2 + 0]);
                atomicAdd(op + ni * 8 + 1, w * acc[mi][ni][half * 2 + 1]);
            }
        }
    }
}

// ---------------- launch ----------------
extern "C" void kernel_launch(void* const* d_in, const int* in_sizes, int n_in,
                              void* d_out, int out_size) {
    const float* x  = (const float*)d_in[0];
    const float* wr = (const float*)d_in[1];
    const float* br = (const float*)d_in[2];
    const float* w1 = (const float*)d_in[3];
    const float* w2 = (const float*)d_in[4];
    float* out = (float*)d_out;
    float* logits = out + (size_t)T_TOK * Dm;

    static int attr_done = 0;
    if (!attr_done) {
        cudaFuncSetAttribute(fc1_kernel, cudaFuncAttributeMaxDynamicSharedMemorySize, 98304);
        cudaFuncSetAttribute(fc2_kernel, cudaFuncAttributeMaxDynamicSharedMemorySize, 98304);
        attr_done = 1;
    }

    prep_kernel<<<5120, 256>>>(out, w1, w2);                 // 1
    router_kernel<<<T_TOK / 4, 64>>>(x, wr, br, logits);     // 2
    dim3 g1(Hm / 128, CAP / 128, Em);
    fc1_kernel<<<g1, 256, 98304>>>();                        // 3
    dim3 g2(Dm / 128, CAP / 128, Em);
    fc2_kernel<<<g2, 256, 98304>>>(out);                     // 4  <-- profiled slot
}

// round 7
// speedup vs baseline: 1.4004x; 1.2856x over previous
#include <cuda_runtime.h>
#include <cuda_bf16.h>
#include <math.h>
#include <stdint.h>

#define T_TOK 2048
#define Dm    512
#define Hm    1024
#define Em    8
#define CAP   2048

// ---------------- scratch (static device globals) ----------------
__device__ int   g_count[Em];
__device__ int   g_list[Em * CAP];
__device__ float g_wt[2 * T_TOK];

__device__ __align__(16) __nv_bfloat16 g_w1hi[Em * Hm * Dm];
__device__ __align__(16) __nv_bfloat16 g_w1lo[Em * Hm * Dm];
__device__ __align__(16) __nv_bfloat16 g_w2hi[Em * Dm * Hm];
__device__ __align__(16) __nv_bfloat16 g_w2lo[Em * Dm * Hm];
__device__ __align__(16) __nv_bfloat16 g_xhi[Em * CAP * Dm];
__device__ __align__(16) __nv_bfloat16 g_xlo[Em * CAP * Dm];
__device__ __align__(16) __nv_bfloat16 g_hhi[Em * CAP * Hm];
__device__ __align__(16) __nv_bfloat16 g_hlo[Em * CAP * Hm];

// ---------------- PTX helpers ----------------
__device__ __forceinline__ uint32_t smem_u32(const void* p) {
    uint32_t a;
    asm("{ .reg .u64 t; cvta.to.shared.u64 t, %1; cvt.u32.u64 %0, t; }" : "=r"(a) : "l"(p));
    return a;
}
__device__ __forceinline__ void cp16(uint32_t dst, const void* src) {
    asm volatile("cp.async.cg.shared.global [%0], [%1], 16;" :: "r"(dst), "l"(src));
}
#define CP_COMMIT() asm volatile("cp.async.commit_group;" ::: "memory")
#define CP_WAIT(n)  asm volatile("cp.async.wait_group %0;" :: "n"(n) : "memory")

__device__ __forceinline__ uint32_t swz(uint32_t off) { return off ^ ((off >> 3) & 0x70); }

__device__ __forceinline__ void ldm_x4(uint32_t* r, uint32_t addr) {
    asm volatile("ldmatrix.sync.aligned.m8n8.x4.shared.b16 {%0,%1,%2,%3}, [%4];"
                 : "=r"(r[0]), "=r"(r[1]), "=r"(r[2]), "=r"(r[3]) : "r"(addr));
}
__device__ __forceinline__ void mma16816(float* c, const uint32_t* a, uint32_t b0, uint32_t b1) {
    asm volatile("mma.sync.aligned.m16n8k16.row.col.f32.bf16.bf16.f32 "
                 "{%0,%1,%2,%3}, {%4,%5,%6,%7}, {%8,%9}, {%0,%1,%2,%3};"
                 : "+f"(c[0]), "+f"(c[1]), "+f"(c[2]), "+f"(c[3])
                 : "r"(a[0]), "r"(a[1]), "r"(a[2]), "r"(a[3]), "r"(b0), "r"(b1));
}

// 256-row x 64-col bf16 tile -> SW128-swizzled smem (512 threads)
__device__ __forceinline__ void stage_tile256(uint32_t sbase, const __nv_bfloat16* src,
                                              int stride, int tid) {
#pragma unroll
    for (int q4 = 0; q4 < 4; q4++) {
        int q = tid + q4 * 512;
        int r = q >> 3, c = q & 7;
        cp16(sbase + swz((uint32_t)(r * 128 + c * 16)), src + (size_t)r * stride + c * 8);
    }
}
// 128-row x 64-col tile (512 threads)
__device__ __forceinline__ void stage_tile128(uint32_t sbase, const __nv_bfloat16* src,
                                              int stride, int tid) {
#pragma unroll
    for (int q4 = 0; q4 < 2; q4++) {
        int q = tid + q4 * 512;
        int r = q >> 3, c = q & 7;
        cp16(sbase + swz((uint32_t)(r * 128 + c * 16)), src + (size_t)r * stride + c * 8);
    }
}

// ---------------- prep: zero out/counts + both weight splits ----------------
__device__ __forceinline__ void split8(const float* f, __nv_bfloat16* h, __nv_bfloat16* l) {
#pragma unroll
    for (int j = 0; j < 8; j++) {
        __nv_bfloat16 hh = __float2bfloat16_rn(f[j]);
        h[j] = hh;
        l[j] = __float2bfloat16_rn(f[j] - __bfloat162float(hh));
    }
}
__device__ __forceinline__ void conv_one(const float* src, __nv_bfloat16* hi,
                                         __nv_bfloat16* lo, int i) {
    const float4* s = (const float4*)src + (size_t)i * 2;
    float4 a = s[0], b = s[1];
    float f[8] = {a.x, a.y, a.z, a.w, b.x, b.y, b.z, b.w};
    alignas(16) __nv_bfloat16 h[8], l[8];
    split8(f, h, l);
    *(uint4*)(hi + (size_t)i * 8) = *(uint4*)h;
    *(uint4*)(lo + (size_t)i * 8) = *(uint4*)l;
}

__global__ void prep_kernel(float* __restrict__ out,
                            const float* __restrict__ w1,
                            const float* __restrict__ w2) {
    int b = blockIdx.x;
    if (b < 1024) {
        ((float4*)out)[b * 256 + threadIdx.x] = make_float4(0.f, 0.f, 0.f, 0.f);
        if (b == 0 && threadIdx.x < Em) g_count[threadIdx.x] = 0;
    } else if (b < 3072) {
        conv_one(w1, g_w1hi, g_w1lo, (b - 1024) * 256 + threadIdx.x);
    } else {
        conv_one(w2, g_w2hi, g_w2lo, (b - 3072) * 256 + threadIdx.x);
    }
}

// ---------------- router + fused gather: 2 tokens per warp ----------------
__global__ __launch_bounds__(64) void router_kernel(const float* __restrict__ x,
                                                    const float* __restrict__ wr,
                                                    const float* __restrict__ br,
                                                    float* __restrict__ logits_out) {
    const int warp = threadIdx.x >> 5;
    const int lane = threadIdx.x & 31;
    const int t0 = (blockIdx.x * 2 + warp) * 2;

    float4 xv[2][4];
#pragma unroll
    for (int s = 0; s < 2; s++) {
        const float4* xv4 = (const float4*)(x) + (size_t)(t0 + s) * (Dm / 4);
#pragma unroll
        for (int i = 0; i < 4; i++) xv[s][i] = xv4[i * 32 + lane];
    }

    float acc[2][Em];
#pragma unroll
    for (int e = 0; e < Em; e++) {
        const float4* wv4 = (const float4*)(wr) + (size_t)e * (Dm / 4);
        float4 wv[4];
#pragma unroll
        for (int i = 0; i < 4; i++) wv[i] = wv4[i * 32 + lane];
#pragma unroll
        for (int s = 0; s < 2; s++) {
            float a = 0.f;
#pragma unroll
            for (int i = 0; i < 4; i++)
                a += xv[s][i].x * wv[i].x + xv[s][i].y * wv[i].y
                   + xv[s][i].z * wv[i].z + xv[s][i].w * wv[i].w;
            acc[s][e] = a;
        }
    }
#pragma unroll
    for (int off = 16; off > 0; off >>= 1)
#pragma unroll
        for (int s = 0; s < 2; s++)
#pragma unroll
            for (int e = 0; e < Em; e++)
                acc[s][e] += __shfl_xor_sync(0xffffffffu, acc[s][e], off);

#pragma unroll
    for (int s = 0; s < 2; s++) {
        const int t = t0 + s;
        float* lg = acc[s];
#pragma unroll
        for (int e = 0; e < Em; e++) lg[e] += br[e];

        int pack0 = 0, pack1 = 0;
        if (lane == 0) {
            *(float4*)(logits_out + (size_t)t * Em)     = make_float4(lg[0], lg[1], lg[2], lg[3]);
            *(float4*)(logits_out + (size_t)t * Em + 4) = make_float4(lg[4], lg[5], lg[6], lg[7]);
            float mx = lg[0];
#pragma unroll
            for (int e = 1; e < Em; e++) mx = fmaxf(mx, lg[e]);
            float p[Em]; float sum = 0.f;
#pragma unroll
            for (int e = 0; e < Em; e++) { p[e] = expf(lg[e] - mx); sum += p[e]; }
            float inv = 1.0f / sum;
#pragma unroll
            for (int e = 0; e < Em; e++) p[e] *= inv;
            int e0 = 0;
#pragma unroll
            for (int e = 1; e < Em; e++) if (p[e] > p[e0]) e0 = e;
            int e1 = (e0 == 0) ? 1 : 0;
#pragma unroll
            for (int e = 0; e < Em; e++) if (e != e0 && p[e] > p[e1]) e1 = e;
            float sum2 = p[e0] + p[e1];
            g_wt[2 * t + 0] = p[e0] / sum2;
            g_wt[2 * t + 1] = p[e1] / sum2;
            int pos0 = atomicAdd(&g_count[e0], 1);
            g_list[e0 * CAP + pos0] = 2 * t + 0;
            int pos1 = atomicAdd(&g_count[e1], 1);
            g_list[e1 * CAP + pos1] = 2 * t + 1;
            pack0 = (e0 << 16) | pos0;
            pack1 = (e1 << 16) | pos1;
        }
        pack0 = __shfl_sync(0xffffffffu, pack0, 0);
        pack1 = __shfl_sync(0xffffffffu, pack1, 0);
        const int e0 = pack0 >> 16, pos0 = pack0 & 0xffff;
        const int e1 = pack1 >> 16, pos1 = pack1 & 0xffff;

        __nv_bfloat16* dh0 = g_xhi + ((size_t)e0 * CAP + pos0) * Dm;
        __nv_bfloat16* dl0 = g_xlo + ((size_t)e0 * CAP + pos0) * Dm;
        __nv_bfloat16* dh1 = g_xhi + ((size_t)e1 * CAP + pos1) * Dm;
        __nv_bfloat16* dl1 = g_xlo + ((size_t)e1 * CAP + pos1) * Dm;
#pragma unroll
        for (int i = 0; i < 4; i++) {
            float f[4] = {xv[s][i].x, xv[s][i].y, xv[s][i].z, xv[s][i].w};
            alignas(8) __nv_bfloat16 h[4], l[4];
#pragma unroll
            for (int j = 0; j < 4; j++) {
                __nv_bfloat16 hh = __float2bfloat16_rn(f[j]);
                h[j] = hh;
                l[j] = __float2bfloat16_rn(f[j] - __bfloat162float(hh));
            }
            int eo = (i * 32 + lane) * 4;
            *(uint2*)(dh0 + eo) = *(uint2*)h;
            *(uint2*)(dl0 + eo) = *(uint2*)l;
            *(uint2*)(dh1 + eo) = *(uint2*)h;
            *(uint2*)(dl1 + eo) = *(uint2*)l;
        }
    }
}

// ---------------- GEMM mainloop: 512 thr, CTA 256x128, 3-stage, single-frag ----------------
extern __shared__ char smx[];

#define STAGE_J(gj, bufi)                                                             \
    do {                                                                              \
        const int seg_ = (gj) >> SEG_SHIFT, kt_ = (gj) & SEG_MASK;                    \
        uint32_t sb2_ = smb + (bufi) * 49152;                                         \
        stage_tile256(sb2_,         Aseg[seg_] + aoff + kt_ * 64, STRIDE, tid);       \
        stage_tile128(sb2_ + 32768, Bseg[seg_] + boff + kt_ * 64, STRIDE, tid);       \
        CP_COMMIT();                                                                  \
    } while (0)

#define GEMM_MAINLOOP(NT, SEG_SHIFT_V, SEG_MASK_V, STRIDE_V, JOFF)                    \
    enum { SEG_SHIFT = SEG_SHIFT_V, SEG_MASK = SEG_MASK_V, STRIDE = STRIDE_V };       \
    uint32_t smb = smem_u32(smx);                                                     \
    STAGE_J((JOFF) + 0, 0);                                                           \
    STAGE_J((JOFF) + 1, 1);                                                           \
    float acc[4][4][4];                                                               \
    _Pragma("unroll") for (int a1 = 0; a1 < 4; a1++)                                  \
    _Pragma("unroll") for (int a2 = 0; a2 < 4; a2++)                                  \
    _Pragma("unroll") for (int a3 = 0; a3 < 4; a3++) acc[a1][a2][a3] = 0.f;           \
    const int lr = lane & 15, lc = lane >> 4;                                         \
    int bc = 0, bs = 2;                                                               \
    for (int i = 0; i < NT; i++) {                                                    \
        if (i < NT - 1) CP_WAIT(1); else CP_WAIT(0);                                  \
        __syncthreads();                                                              \
        if (i + 2 < NT) { STAGE_J((JOFF) + i + 2, bs); bs = (bs == 2) ? 0 : bs + 1; } \
        uint32_t sa = smb + bc * 49152, sbb = sa + 32768;                             \
        bc = (bc == 2) ? 0 : bc + 1;                                                  \
        _Pragma("unroll")                                                             \
        for (int kk16 = 0; kk16 < 4; kk16++) {                                        \
            uint32_t af[4][4];                                                        \
            _Pragma("unroll")                                                         \
            for (int mi = 0; mi < 4; mi++) {                                          \
                uint32_t off = (uint32_t)((warpM * 64 + mi * 16 + lr) * 128           \
                                          + (kk16 * 2 + lc) * 16);                    \
                ldm_x4(af[mi], sa + swz(off));                                        \
            }                                                                         \
            uint32_t bfr[2][4];                                                       \
            _Pragma("unroll")                                                         \
            for (int nj = 0; nj < 2; nj++) {                                          \
                uint32_t off = (uint32_t)((warpN * 32 + nj * 16 + lr) * 128           \
                                          + (kk16 * 2 + lc) * 16);                    \
                ldm_x4(bfr[nj], sbb + swz(off));                                      \
            }                                                                         \
            _Pragma("unroll")                                                         \
            for (int mi = 0; mi < 4; mi++)                                            \
                _Pragma("unroll")                                                     \
                for (int ni = 0; ni < 4; ni++) {                                      \
                    const int nj = ni >> 1, sub = ni & 1;                             \
                    mma16816(acc[mi][ni], af[mi], bfr[nj][sub], bfr[nj][sub + 2]);    \
                }                                                                     \
        }                                                                             \
    }

// ---------------- fc1: h = gelu(X @ W1^T), CTA 256 rows x 128 cols ----------------
__global__ __launch_bounds__(512) void fc1_kernel() {
    const int e = blockIdx.z;
    const int cnt = g_count[e];
    const int rowbase = blockIdx.y * 256;
    if (rowbase >= cnt) return;
    const int nbase = blockIdx.x * 128;

    const int tid = threadIdx.x;
    const int wid = tid >> 5, lane = tid & 31;
    const int warpM = wid >> 2, warpN = wid & 3;   // 4x4 warps

    const __nv_bfloat16* Aseg[3] = {g_xhi, g_xhi, g_xlo};
    const __nv_bfloat16* Bseg[3] = {g_w1hi, g_w1lo, g_w1hi};
    const size_t aoff = ((size_t)e * CAP + rowbase) * Dm;
    const size_t boff = ((size_t)e * Hm + nbase) * Dm;

    GEMM_MAINLOOP(24, 3, 7, Dm, 0)

    const int r0 = lane >> 2, c0 = (lane & 3) * 2;
#pragma unroll
    for (int mi = 0; mi < 4; mi++) {
#pragma unroll
        for (int half = 0; half < 2; half++) {
            int row = rowbase + warpM * 64 + mi * 16 + r0 + half * 8;
            size_t rg = ((size_t)e * CAP + row) * Hm + nbase + warpN * 32 + c0;
#pragma unroll
            for (int ni = 0; ni < 4; ni++) {
                float v0 = acc[mi][ni][half * 2 + 0];
                float v1 = acc[mi][ni][half * 2 + 1];
                float gg0 = 0.5f * v0 * (1.0f + erff(v0 * 0.70710678118654752f));
                float gg1 = 0.5f * v1 * (1.0f + erff(v1 * 0.70710678118654752f));
                __nv_bfloat16 h0 = __float2bfloat16_rn(gg0);
                __nv_bfloat16 h1 = __float2bfloat16_rn(gg1);
                __nv_bfloat16 l0 = __float2bfloat16_rn(gg0 - __bfloat162float(h0));
                __nv_bfloat16 l1 = __float2bfloat16_rn(gg1 - __bfloat162float(h1));
                uint32_t hp = (uint32_t)*(uint16_t*)&h0 | ((uint32_t)*(uint16_t*)&h1 << 16);
                uint32_t lp = (uint32_t)*(uint16_t*)&l0 | ((uint32_t)*(uint16_t*)&l1 << 16);
                *(uint32_t*)(g_hhi + rg + ni * 8) = hp;
                *(uint32_t*)(g_hlo + rg + ni * 8) = lp;
            }
        }
    }
}

// ---------------- fc2: out[tok] += w * (H @ W2^T), split-K x2 ----------------
__global__ __launch_bounds__(512) void fc2_kernel(float* __restrict__ out) {
    const int e = blockIdx.z;
    const int cnt = g_count[e];
    const int rowbase = blockIdx.y * 256;
    if (rowbase >= cnt) return;
    const int ksplit = blockIdx.x >> 2;            // 0 or 1
    const int nbase = (blockIdx.x & 3) * 128;

    const int tid = threadIdx.x;
    const int wid = tid >> 5, lane = tid & 31;
    const int warpM = wid >> 2, warpN = wid & 3;

    const __nv_bfloat16* Aseg[3] = {g_hhi, g_hhi, g_hlo};
    const __nv_bfloat16* Bseg[3] = {g_w2hi, g_w2lo, g_w2hi};
    const size_t aoff = ((size_t)e * CAP + rowbase) * Hm;
    const size_t boff = ((size_t)e * Dm + nbase) * Hm;

    GEMM_MAINLOOP(24, 4, 15, Hm, ksplit * 24)      // halves of 48 k-tiles

    const int r0 = lane >> 2, c0 = (lane & 3) * 2;
#pragma unroll
    for (int mi = 0; mi < 4; mi++) {
#pragma unroll
        for (int half = 0; half < 2; half++) {
            int pos = rowbase + warpM * 64 + mi * 16 + r0 + half * 8;
            if (pos >= cnt) continue;
            int entry = g_list[e * CAP + pos];
            float w = g_wt[entry];
            int tok = entry >> 1;
            float* op = out + (size_t)tok * Dm + nbase + warpN * 32 + c0;
#pragma unroll
            for (int ni = 0; ni < 4; ni++) {
                atomicAdd(op + ni * 8,     w * acc[mi][ni][half * 2 + 0]);
                atomicAdd(op + ni * 8 + 1, w * acc[mi][ni][half * 2 + 1]);
            }
        }
    }
}

// ---------------- launch ----------------
extern "C" void kernel_launch(void* const* d_in, const int* in_sizes, int n_in,
                              void* d_out, int out_size) {
    const float* x  = (const float*)d_in[0];
    const float* wr = (const float*)d_in[1];
    const float* br = (const float*)d_in[2];
    const float* w1 = (const float*)d_in[3];
    const float* w2 = (const float*)d_in[4];
    float* out = (float*)d_out;
    float* logits = out + (size_t)T_TOK * Dm;

    static int attr_done = 0;
    if (!attr_done) {
        cudaFuncSetAttribute(fc1_kernel, cudaFuncAttributeMaxDynamicSharedMemorySize, 147456);
        cudaFuncSetAttribute(fc2_kernel, cudaFuncAttributeMaxDynamicSharedMemorySize, 147456);
        attr_done = 1;
    }

    prep_kernel<<<5120, 256>>>(out, w1, w2);                 // 1
    router_kernel<<<T_TOK / 4, 64>>>(x, wr, br, logits);     // 2
    dim3 g1(Hm / 128, CAP / 256, Em);                        // (8, 8, 8)
    fc1_kernel<<<g1, 512, 147456>>>();                       // 3
    dim3 g2((Dm / 128) * 2, CAP / 256, Em);                  // (8, 8, 8)
    fc2_kernel<<<g2, 512, 147456>>>(out);                    // 4  <-- profiled slot
}

// round 8
// speedup vs baseline: 1.4525x; 1.0372x over previous
#include <cuda_runtime.h>
#include <cuda_bf16.h>
#include <math.h>
#include <stdint.h>

#define T_TOK 2048
#define Dm    512
#define Hm    1024
#define Em    8
#define CAP   2048

// ---------------- scratch (static device globals) ----------------
__device__ int   g_count[Em];
__device__ int   g_list[Em * CAP];
__device__ float g_wt[2 * T_TOK];

__device__ __align__(16) __nv_bfloat16 g_w1hi[Em * Hm * Dm];
__device__ __align__(16) __nv_bfloat16 g_w1lo[Em * Hm * Dm];
__device__ __align__(16) __nv_bfloat16 g_w2hi[Em * Dm * Hm];
__device__ __align__(16) __nv_bfloat16 g_w2lo[Em * Dm * Hm];
__device__ __align__(16) __nv_bfloat16 g_xhi[Em * CAP * Dm];
__device__ __align__(16) __nv_bfloat16 g_xlo[Em * CAP * Dm];
__device__ __align__(16) __nv_bfloat16 g_hhi[Em * CAP * Hm];
__device__ __align__(16) __nv_bfloat16 g_hlo[Em * CAP * Hm];

// ---------------- PTX helpers ----------------
__device__ __forceinline__ uint32_t smem_u32(const void* p) {
    uint32_t a;
    asm("{ .reg .u64 t; cvta.to.shared.u64 t, %1; cvt.u32.u64 %0, t; }" : "=r"(a) : "l"(p));
    return a;
}
__device__ __forceinline__ void cp16(uint32_t dst, const void* src) {
    asm volatile("cp.async.cg.shared.global [%0], [%1], 16;" :: "r"(dst), "l"(src));
}
#define CP_COMMIT() asm volatile("cp.async.commit_group;" ::: "memory")
#define CP_WAIT(n)  asm volatile("cp.async.wait_group %0;" :: "n"(n) : "memory")

__device__ __forceinline__ uint32_t swz(uint32_t off) { return off ^ ((off >> 3) & 0x70); }

__device__ __forceinline__ void ldm_x4(uint32_t* r, uint32_t addr) {
    asm volatile("ldmatrix.sync.aligned.m8n8.x4.shared.b16 {%0,%1,%2,%3}, [%4];"
                 : "=r"(r[0]), "=r"(r[1]), "=r"(r[2]), "=r"(r[3]) : "r"(addr));
}
__device__ __forceinline__ void mma16816(float* c, const uint32_t* a, uint32_t b0, uint32_t b1) {
    asm volatile("mma.sync.aligned.m16n8k16.row.col.f32.bf16.bf16.f32 "
                 "{%0,%1,%2,%3}, {%4,%5,%6,%7}, {%8,%9}, {%0,%1,%2,%3};"
                 : "+f"(c[0]), "+f"(c[1]), "+f"(c[2]), "+f"(c[3])
                 : "r"(a[0]), "r"(a[1]), "r"(a[2]), "r"(a[3]), "r"(b0), "r"(b1));
}

__device__ __forceinline__ void stage_tile256(uint32_t sbase, const __nv_bfloat16* src,
                                              int stride, int tid) {
#pragma unroll
    for (int q4 = 0; q4 < 4; q4++) {
        int q = tid + q4 * 512;
        int r = q >> 3, c = q & 7;
        cp16(sbase + swz((uint32_t)(r * 128 + c * 16)), src + (size_t)r * stride + c * 8);
    }
}
__device__ __forceinline__ void stage_tile128(uint32_t sbase, const __nv_bfloat16* src,
                                              int stride, int tid) {
#pragma unroll
    for (int q4 = 0; q4 < 2; q4++) {
        int q = tid + q4 * 512;
        int r = q >> 3, c = q & 7;
        cp16(sbase + swz((uint32_t)(r * 128 + c * 16)), src + (size_t)r * stride + c * 8);
    }
}

// ---------------- helpers for prep ----------------
__device__ __forceinline__ void split8(const float* f, __nv_bfloat16* h, __nv_bfloat16* l) {
#pragma unroll
    for (int j = 0; j < 8; j++) {
        __nv_bfloat16 hh = __float2bfloat16_rn(f[j]);
        h[j] = hh;
        l[j] = __float2bfloat16_rn(f[j] - __bfloat162float(hh));
    }
}
__device__ __forceinline__ void conv_one(const float* src, __nv_bfloat16* hi,
                                         __nv_bfloat16* lo, int i) {
    const float4* s = (const float4*)src + (size_t)i * 2;
    float4 a = s[0], b = s[1];
    float f[8] = {a.x, a.y, a.z, a.w, b.x, b.y, b.z, b.w};
    alignas(16) __nv_bfloat16 h[8], l[8];
    split8(f, h, l);
    *(uint4*)(hi + (size_t)i * 8) = *(uint4*)h;
    *(uint4*)(lo + (size_t)i * 8) = *(uint4*)l;
}

// ---------------- fused prep + router ----------------
// blocks [0,128): router (8 warps x 2 tokens each = 16 tokens/block)
// blocks [128,1152): zero out[T*D]
// blocks [1152,3200): split w1 ; [3200,5248): split w2
__global__ __launch_bounds__(256) void prep_router_kernel(const float* __restrict__ x,
                                                          const float* __restrict__ wr,
                                                          const float* __restrict__ br,
                                                          const float* __restrict__ w1,
                                                          const float* __restrict__ w2,
                                                          float* __restrict__ out,
                                                          float* __restrict__ logits_out) {
    const int b = blockIdx.x;
    if (b >= 128) {
        if (b < 1152) {
            ((float4*)out)[(b - 128) * 256 + threadIdx.x] = make_float4(0.f, 0.f, 0.f, 0.f);
        } else if (b < 3200) {
            conv_one(w1, g_w1hi, g_w1lo, (b - 1152) * 256 + threadIdx.x);
        } else {
            conv_one(w2, g_w2hi, g_w2lo, (b - 3200) * 256 + threadIdx.x);
        }
        return;
    }

    const int warp = threadIdx.x >> 5;
    const int lane = threadIdx.x & 31;
    const int t0 = (b * 8 + warp) * 2;

    float4 xv[2][4];
#pragma unroll
    for (int s = 0; s < 2; s++) {
        const float4* xv4 = (const float4*)(x) + (size_t)(t0 + s) * (Dm / 4);
#pragma unroll
        for (int i = 0; i < 4; i++) xv[s][i] = xv4[i * 32 + lane];
    }

    float acc[2][Em];
#pragma unroll
    for (int e = 0; e < Em; e++) {
        const float4* wv4 = (const float4*)(wr) + (size_t)e * (Dm / 4);
        float4 wv[4];
#pragma unroll
        for (int i = 0; i < 4; i++) wv[i] = wv4[i * 32 + lane];
#pragma unroll
        for (int s = 0; s < 2; s++) {
            float a = 0.f;
#pragma unroll
            for (int i = 0; i < 4; i++)
                a += xv[s][i].x * wv[i].x + xv[s][i].y * wv[i].y
                   + xv[s][i].z * wv[i].z + xv[s][i].w * wv[i].w;
            acc[s][e] = a;
        }
    }
#pragma unroll
    for (int off = 16; off > 0; off >>= 1)
#pragma unroll
        for (int s = 0; s < 2; s++)
#pragma unroll
            for (int e = 0; e < Em; e++)
                acc[s][e] += __shfl_xor_sync(0xffffffffu, acc[s][e], off);

#pragma unroll
    for (int s = 0; s < 2; s++) {
        const int t = t0 + s;
        float* lg = acc[s];
#pragma unroll
        for (int e = 0; e < Em; e++) lg[e] += br[e];

        int pack0 = 0, pack1 = 0;
        if (lane == 0) {
            *(float4*)(logits_out + (size_t)t * Em)     = make_float4(lg[0], lg[1], lg[2], lg[3]);
            *(float4*)(logits_out + (size_t)t * Em + 4) = make_float4(lg[4], lg[5], lg[6], lg[7]);
            float mx = lg[0];
#pragma unroll
            for (int e = 1; e < Em; e++) mx = fmaxf(mx, lg[e]);
            float p[Em]; float sum = 0.f;
#pragma unroll
            for (int e = 0; e < Em; e++) { p[e] = expf(lg[e] - mx); sum += p[e]; }
            float inv = 1.0f / sum;
#pragma unroll
            for (int e = 0; e < Em; e++) p[e] *= inv;
            int e0 = 0;
#pragma unroll
            for (int e = 1; e < Em; e++) if (p[e] > p[e0]) e0 = e;
            int e1 = (e0 == 0) ? 1 : 0;
#pragma unroll
            for (int e = 0; e < Em; e++) if (e != e0 && p[e] > p[e1]) e1 = e;
            float sum2 = p[e0] + p[e1];
            g_wt[2 * t + 0] = p[e0] / sum2;
            g_wt[2 * t + 1] = p[e1] / sum2;
            int pos0 = atomicAdd(&g_count[e0], 1);
            g_list[e0 * CAP + pos0] = 2 * t + 0;
            int pos1 = atomicAdd(&g_count[e1], 1);
            g_list[e1 * CAP + pos1] = 2 * t + 1;
            pack0 = (e0 << 16) | pos0;
            pack1 = (e1 << 16) | pos1;
        }
        pack0 = __shfl_sync(0xffffffffu, pack0, 0);
        pack1 = __shfl_sync(0xffffffffu, pack1, 0);
        const int e0 = pack0 >> 16, pos0 = pack0 & 0xffff;
        const int e1 = pack1 >> 16, pos1 = pack1 & 0xffff;

        __nv_bfloat16* dh0 = g_xhi + ((size_t)e0 * CAP + pos0) * Dm;
        __nv_bfloat16* dl0 = g_xlo + ((size_t)e0 * CAP + pos0) * Dm;
        __nv_bfloat16* dh1 = g_xhi + ((size_t)e1 * CAP + pos1) * Dm;
        __nv_bfloat16* dl1 = g_xlo + ((size_t)e1 * CAP + pos1) * Dm;
#pragma unroll
        for (int i = 0; i < 4; i++) {
            float f[4] = {xv[s][i].x, xv[s][i].y, xv[s][i].z, xv[s][i].w};
            alignas(8) __nv_bfloat16 h[4], l[4];
#pragma unroll
            for (int j = 0; j < 4; j++) {
                __nv_bfloat16 hh = __float2bfloat16_rn(f[j]);
                h[j] = hh;
                l[j] = __float2bfloat16_rn(f[j] - __bfloat162float(hh));
            }
            int eo = (i * 32 + lane) * 4;
            *(uint2*)(dh0 + eo) = *(uint2*)h;
            *(uint2*)(dl0 + eo) = *(uint2*)l;
            *(uint2*)(dh1 + eo) = *(uint2*)h;
            *(uint2*)(dl1 + eo) = *(uint2*)l;
        }
    }
}

// ---------------- GEMM mainloop: 512 thr, CTA 256x128, 4 buffers, 2 tiles/barrier ----------------
extern __shared__ char smx[];

#define STAGE_J(gj, bufi)                                                             \
    do {                                                                              \
        const int seg_ = (gj) >> SEG_SHIFT, kt_ = (gj) & SEG_MASK;                    \
        uint32_t sb2_ = smb + (bufi) * 49152;                                         \
        stage_tile256(sb2_,         Aseg[seg_] + aoff + kt_ * 64, STRIDE, tid);       \
        stage_tile128(sb2_ + 32768, Bseg[seg_] + boff + kt_ * 64, STRIDE, tid);       \
        CP_COMMIT();                                                                  \
    } while (0)

#define COMPUTE_TILE(bufidx)                                                          \
    do {                                                                              \
        uint32_t sa_ = smb + (bufidx) * 49152, sbb_ = sa_ + 32768;                    \
        _Pragma("unroll")                                                             \
        for (int kk16 = 0; kk16 < 4; kk16++) {                                        \
            uint32_t af[4][4];                                                        \
            _Pragma("unroll")                                                         \
            for (int mi = 0; mi < 4; mi++) {                                          \
                uint32_t off = (uint32_t)((warpM * 64 + mi * 16 + lr) * 128           \
                                          + (kk16 * 2 + lc) * 16);                    \
                ldm_x4(af[mi], sa_ + swz(off));                                       \
            }                                                                         \
            uint32_t bfr[2][4];                                                       \
            _Pragma("unroll")                                                         \
            for (int nj = 0; nj < 2; nj++) {                                          \
                uint32_t off = (uint32_t)((warpN * 32 + nj * 16 + lr) * 128           \
                                          + (kk16 * 2 + lc) * 16);                    \
                ldm_x4(bfr[nj], sbb_ + swz(off));                                     \
            }                                                                         \
            _Pragma("unroll")                                                         \
            for (int mi = 0; mi < 4; mi++)                                            \
                _Pragma("unroll")                                                     \
                for (int ni = 0; ni < 4; ni++) {                                      \
                    const int nj = ni >> 1, sub = ni & 1;                             \
                    mma16816(acc[mi][ni], af[mi], bfr[nj][sub], bfr[nj][sub + 2]);    \
                }                                                                     \
        }                                                                             \
    } while (0)

#define GEMM_MAINLOOP(NT, SEG_SHIFT_V, SEG_MASK_V, STRIDE_V, JOFF)                    \
    enum { SEG_SHIFT = SEG_SHIFT_V, SEG_MASK = SEG_MASK_V, STRIDE = STRIDE_V };       \
    uint32_t smb = smem_u32(smx);                                                     \
    STAGE_J((JOFF) + 0, 0);                                                           \
    STAGE_J((JOFF) + 1, 1);                                                           \
    float acc[4][4][4];                                                               \
    _Pragma("unroll") for (int a1 = 0; a1 < 4; a1++)                                  \
    _Pragma("unroll") for (int a2 = 0; a2 < 4; a2++)                                  \
    _Pragma("unroll") for (int a3 = 0; a3 < 4; a3++) acc[a1][a2][a3] = 0.f;           \
    const int lr = lane & 15, lc = lane >> 4;                                         \
    for (int i = 0; i < NT; i += 2) {                                                 \
        CP_WAIT(0);                                                                   \
        __syncthreads();                                                              \
        if (i + 2 < NT) { STAGE_J((JOFF) + i + 2, (i + 2) & 3);                       \
                          STAGE_J((JOFF) + i + 3, (i + 3) & 3); }                     \
        COMPUTE_TILE(i & 3);                                                          \
        COMPUTE_TILE((i + 1) & 3);                                                    \
    }

// ---------------- fc1: h = gelu(X @ W1^T), CTA 256 x 128 ----------------
__global__ __launch_bounds__(512) void fc1_kernel() {
    const int e = blockIdx.z;
    const int cnt = g_count[e];
    const int rowbase = blockIdx.y * 256;
    if (rowbase >= cnt) return;
    const int nbase = blockIdx.x * 128;

    const int tid = threadIdx.x;
    const int wid = tid >> 5, lane = tid & 31;
    const int warpM = wid >> 2, warpN = wid & 3;

    const __nv_bfloat16* Aseg[3] = {g_xhi, g_xhi, g_xlo};
    const __nv_bfloat16* Bseg[3] = {g_w1hi, g_w1lo, g_w1hi};
    const size_t aoff = ((size_t)e * CAP + rowbase) * Dm;
    const size_t boff = ((size_t)e * Hm + nbase) * Dm;

    GEMM_MAINLOOP(24, 3, 7, Dm, 0)

    const int r0 = lane >> 2, c0 = (lane & 3) * 2;
#pragma unroll
    for (int mi = 0; mi < 4; mi++) {
#pragma unroll
        for (int half = 0; half < 2; half++) {
            int row = rowbase + warpM * 64 + mi * 16 + r0 + half * 8;
            size_t rg = ((size_t)e * CAP + row) * Hm + nbase + warpN * 32 + c0;
#pragma unroll
            for (int ni = 0; ni < 4; ni++) {
                float v0 = acc[mi][ni][half * 2 + 0];
                float v1 = acc[mi][ni][half * 2 + 1];
                float gg0 = 0.5f * v0 * (1.0f + erff(v0 * 0.70710678118654752f));
                float gg1 = 0.5f * v1 * (1.0f + erff(v1 * 0.70710678118654752f));
                __nv_bfloat16 h0 = __float2bfloat16_rn(gg0);
                __nv_bfloat16 h1 = __float2bfloat16_rn(gg1);
                __nv_bfloat16 l0 = __float2bfloat16_rn(gg0 - __bfloat162float(h0));
                __nv_bfloat16 l1 = __float2bfloat16_rn(gg1 - __bfloat162float(h1));
                uint32_t hp = (uint32_t)*(uint16_t*)&h0 | ((uint32_t)*(uint16_t*)&h1 << 16);
                uint32_t lp = (uint32_t)*(uint16_t*)&l0 | ((uint32_t)*(uint16_t*)&l1 << 16);
                *(uint32_t*)(g_hhi + rg + ni * 8) = hp;
                *(uint32_t*)(g_hlo + rg + ni * 8) = lp;
            }
        }
    }
}

// ---------------- fc2: out[tok] += w * (H @ W2^T), split-K x2 ----------------
__global__ __launch_bounds__(512) void fc2_kernel(float* __restrict__ out) {
    const int e = blockIdx.z;
    const int cnt = g_count[e];
    const int rowbase = blockIdx.y * 256;
    if (rowbase >= cnt) return;
    const int ksplit = blockIdx.x >> 2;
    const int nbase = (blockIdx.x & 3) * 128;

    const int tid = threadIdx.x;
    const int wid = tid >> 5, lane = tid & 31;
    const int warpM = wid >> 2, warpN = wid & 3;

    const __nv_bfloat16* Aseg[3] = {g_hhi, g_hhi, g_hlo};
    const __nv_bfloat16* Bseg[3] = {g_w2hi, g_w2lo, g_w2hi};
    const size_t aoff = ((size_t)e * CAP + rowbase) * Hm;
    const size_t boff = ((size_t)e * Dm + nbase) * Hm;

    GEMM_MAINLOOP(24, 4, 15, Hm, ksplit * 24)

    const int r0 = lane >> 2, c0 = (lane & 3) * 2;
#pragma unroll
    for (int mi = 0; mi < 4; mi++) {
#pragma unroll
        for (int half = 0; half < 2; half++) {
            int pos = rowbase + warpM * 64 + mi * 16 + r0 + half * 8;
            if (pos >= cnt) continue;
            int entry = g_list[e * CAP + pos];
            float w = g_wt[entry];
            int tok = entry >> 1;
            float* op = out + (size_t)tok * Dm + nbase + warpN * 32 + c0;
#pragma unroll
            for (int ni = 0; ni < 4; ni++) {
                atomicAdd(op + ni * 8,     w * acc[mi][ni][half * 2 + 0]);
                atomicAdd(op + ni * 8 + 1, w * acc[mi][ni][half * 2 + 1]);
            }
        }
    }
}

// ---------------- launch ----------------
extern "C" void kernel_launch(void* const* d_in, const int* in_sizes, int n_in,
                              void* d_out, int out_size) {
    const float* x  = (const float*)d_in[0];
    const float* wr = (const float*)d_in[1];
    const float* br = (const float*)d_in[2];
    const float* w1 = (const float*)d_in[3];
    const float* w2 = (const float*)d_in[4];
    float* out = (float*)d_out;
    float* logits = out + (size_t)T_TOK * Dm;

    static void* count_ptr = nullptr;
    static int attr_done = 0;
    if (!attr_done) {
        cudaFuncSetAttribute(fc1_kernel, cudaFuncAttributeMaxDynamicSharedMemorySize, 196608);
        cudaFuncSetAttribute(fc2_kernel, cudaFuncAttributeMaxDynamicSharedMemorySize, 196608);
        cudaGetSymbolAddress(&count_ptr, g_count);
        attr_done = 1;
    }

    cudaMemsetAsync(count_ptr, 0, Em * sizeof(int));                     // memset node
    prep_router_kernel<<<5248, 256>>>(x, wr, br, w1, w2, out, logits);   // 1
    dim3 g1(Hm / 128, CAP / 256, Em);
    fc1_kernel<<<g1, 512, 196608>>>();                                   // 2
    dim3 g2((Dm / 128) * 2, CAP / 256, Em);
    fc2_kernel<<<g2, 512, 196608>>>(out);                                // 3
}

// round 9
// speedup vs baseline: 1.4763x; 1.0164x over previous
#include <cuda_runtime.h>
#include <cuda_bf16.h>
#include <math.h>
#include <stdint.h>

#define T_TOK 2048
#define Dm    512
#define Hm    1024
#define Em    8
#define CAP   2048

// ---------------- scratch (static device globals) ----------------
__device__ int   g_count[Em];
__device__ int   g_list[Em * CAP];
__device__ float g_wt[2 * T_TOK];

__device__ __align__(16) __nv_bfloat16 g_w1hi[Em * Hm * Dm];
__device__ __align__(16) __nv_bfloat16 g_w1lo[Em * Hm * Dm];
__device__ __align__(16) __nv_bfloat16 g_w2hi[Em * Dm * Hm];
__device__ __align__(16) __nv_bfloat16 g_w2lo[Em * Dm * Hm];
__device__ __align__(16) __nv_bfloat16 g_xhi[Em * CAP * Dm];
__device__ __align__(16) __nv_bfloat16 g_xlo[Em * CAP * Dm];
__device__ __align__(16) __nv_bfloat16 g_hhi[Em * CAP * Hm];
__device__ __align__(16) __nv_bfloat16 g_hlo[Em * CAP * Hm];

// ---------------- PTX helpers ----------------
__device__ __forceinline__ uint32_t smem_u32(const void* p) {
    uint32_t a;
    asm("{ .reg .u64 t; cvta.to.shared.u64 t, %1; cvt.u32.u64 %0, t; }" : "=r"(a) : "l"(p));
    return a;
}
__device__ __forceinline__ void cp16(uint32_t dst, const void* src) {
    asm volatile("cp.async.cg.shared.global [%0], [%1], 16;" :: "r"(dst), "l"(src));
}
#define CP_COMMIT() asm volatile("cp.async.commit_group;" ::: "memory")
#define CP_WAIT(n)  asm volatile("cp.async.wait_group %0;" :: "n"(n) : "memory")

__device__ __forceinline__ uint32_t swz(uint32_t off) { return off ^ ((off >> 3) & 0x70); }

__device__ __forceinline__ void ldm_x4(uint32_t* r, uint32_t addr) {
    asm volatile("ldmatrix.sync.aligned.m8n8.x4.shared.b16 {%0,%1,%2,%3}, [%4];"
                 : "=r"(r[0]), "=r"(r[1]), "=r"(r[2]), "=r"(r[3]) : "r"(addr));
}
__device__ __forceinline__ void mma16816(float* c, const uint32_t* a, uint32_t b0, uint32_t b1) {
    asm volatile("mma.sync.aligned.m16n8k16.row.col.f32.bf16.bf16.f32 "
                 "{%0,%1,%2,%3}, {%4,%5,%6,%7}, {%8,%9}, {%0,%1,%2,%3};"
                 : "+f"(c[0]), "+f"(c[1]), "+f"(c[2]), "+f"(c[3])
                 : "r"(a[0]), "r"(a[1]), "r"(a[2]), "r"(a[3]), "r"(b0), "r"(b1));
}

__device__ __forceinline__ void stage_tile256(uint32_t sbase, const __nv_bfloat16* src,
                                              int stride, int tid) {
#pragma unroll
    for (int q4 = 0; q4 < 4; q4++) {
        int q = tid + q4 * 512;
        int r = q >> 3, c = q & 7;
        cp16(sbase + swz((uint32_t)(r * 128 + c * 16)), src + (size_t)r * stride + c * 8);
    }
}
__device__ __forceinline__ void stage_tile128(uint32_t sbase, const __nv_bfloat16* src,
                                              int stride, int tid) {
#pragma unroll
    for (int q4 = 0; q4 < 2; q4++) {
        int q = tid + q4 * 512;
        int r = q >> 3, c = q & 7;
        cp16(sbase + swz((uint32_t)(r * 128 + c * 16)), src + (size_t)r * stride + c * 8);
    }
}

// ---------------- helpers for prep ----------------
__device__ __forceinline__ void split8(const float* f, __nv_bfloat16* h, __nv_bfloat16* l) {
#pragma unroll
    for (int j = 0; j < 8; j++) {
        __nv_bfloat16 hh = __float2bfloat16_rn(f[j]);
        h[j] = hh;
        l[j] = __float2bfloat16_rn(f[j] - __bfloat162float(hh));
    }
}
// 2 groups of 8 floats per thread, loads hoisted (MLP=4)
__device__ __forceinline__ void conv_two(const float* src, __nv_bfloat16* hi,
                                         __nv_bfloat16* lo, int g0) {
    const int g1 = g0 + 256;
    const float4* s0 = (const float4*)src + (size_t)g0 * 2;
    const float4* s1 = (const float4*)src + (size_t)g1 * 2;
    float4 a0 = s0[0], b0 = s0[1], a1 = s1[0], b1 = s1[1];
    float f0[8] = {a0.x, a0.y, a0.z, a0.w, b0.x, b0.y, b0.z, b0.w};
    float f1[8] = {a1.x, a1.y, a1.z, a1.w, b1.x, b1.y, b1.z, b1.w};
    alignas(16) __nv_bfloat16 h0[8], l0[8], h1[8], l1[8];
    split8(f0, h0, l0);
    split8(f1, h1, l1);
    *(uint4*)(hi + (size_t)g0 * 8) = *(uint4*)h0;
    *(uint4*)(lo + (size_t)g0 * 8) = *(uint4*)l0;
    *(uint4*)(hi + (size_t)g1 * 8) = *(uint4*)h1;
    *(uint4*)(lo + (size_t)g1 * 8) = *(uint4*)l1;
}

// ---------------- fused prep + router ----------------
// blocks [0,128): router; [128,1152): split w1; [1152,2176): split w2
__global__ __launch_bounds__(256) void prep_router_kernel(const float* __restrict__ x,
                                                          const float* __restrict__ wr,
                                                          const float* __restrict__ br,
                                                          const float* __restrict__ w1,
                                                          const float* __restrict__ w2,
                                                          float* __restrict__ logits_out) {
    const int b = blockIdx.x;
    if (b >= 128) {
        if (b < 1152) {
            conv_two(w1, g_w1hi, g_w1lo, (b - 128) * 512 + threadIdx.x);
        } else {
            conv_two(w2, g_w2hi, g_w2lo, (b - 1152) * 512 + threadIdx.x);
        }
        return;
    }

    const int warp = threadIdx.x >> 5;
    const int lane = threadIdx.x & 31;
    const int t0 = (b * 8 + warp) * 2;

    float4 xv[2][4];
#pragma unroll
    for (int s = 0; s < 2; s++) {
        const float4* xv4 = (const float4*)(x) + (size_t)(t0 + s) * (Dm / 4);
#pragma unroll
        for (int i = 0; i < 4; i++) xv[s][i] = xv4[i * 32 + lane];
    }

    float acc[2][Em];
#pragma unroll
    for (int e = 0; e < Em; e++) {
        const float4* wv4 = (const float4*)(wr) + (size_t)e * (Dm / 4);
        float4 wv[4];
#pragma unroll
        for (int i = 0; i < 4; i++) wv[i] = wv4[i * 32 + lane];
#pragma unroll
        for (int s = 0; s < 2; s++) {
            float a = 0.f;
#pragma unroll
            for (int i = 0; i < 4; i++)
                a += xv[s][i].x * wv[i].x + xv[s][i].y * wv[i].y
                   + xv[s][i].z * wv[i].z + xv[s][i].w * wv[i].w;
            acc[s][e] = a;
        }
    }
#pragma unroll
    for (int off = 16; off > 0; off >>= 1)
#pragma unroll
        for (int s = 0; s < 2; s++)
#pragma unroll
            for (int e = 0; e < Em; e++)
                acc[s][e] += __shfl_xor_sync(0xffffffffu, acc[s][e], off);

#pragma unroll
    for (int s = 0; s < 2; s++) {
        const int t = t0 + s;
        float* lg = acc[s];
#pragma unroll
        for (int e = 0; e < Em; e++) lg[e] += br[e];

        int pack0 = 0, pack1 = 0;
        if (lane == 0) {
            *(float4*)(logits_out + (size_t)t * Em)     = make_float4(lg[0], lg[1], lg[2], lg[3]);
            *(float4*)(logits_out + (size_t)t * Em + 4) = make_float4(lg[4], lg[5], lg[6], lg[7]);
            float mx = lg[0];
#pragma unroll
            for (int e = 1; e < Em; e++) mx = fmaxf(mx, lg[e]);
            float p[Em]; float sum = 0.f;
#pragma unroll
            for (int e = 0; e < Em; e++) { p[e] = expf(lg[e] - mx); sum += p[e]; }
            float inv = 1.0f / sum;
#pragma unroll
            for (int e = 0; e < Em; e++) p[e] *= inv;
            int e0 = 0;
#pragma unroll
            for (int e = 1; e < Em; e++) if (p[e] > p[e0]) e0 = e;
            int e1 = (e0 == 0) ? 1 : 0;
#pragma unroll
            for (int e = 0; e < Em; e++) if (e != e0 && p[e] > p[e1]) e1 = e;
            float sum2 = p[e0] + p[e1];
            g_wt[2 * t + 0] = p[e0] / sum2;
            g_wt[2 * t + 1] = p[e1] / sum2;
            int pos0 = atomicAdd(&g_count[e0], 1);
            g_list[e0 * CAP + pos0] = 2 * t + 0;
            int pos1 = atomicAdd(&g_count[e1], 1);
            g_list[e1 * CAP + pos1] = 2 * t + 1;
            pack0 = (e0 << 16) | pos0;
            pack1 = (e1 << 16) | pos1;
        }
        pack0 = __shfl_sync(0xffffffffu, pack0, 0);
        pack1 = __shfl_sync(0xffffffffu, pack1, 0);
        const int e0 = pack0 >> 16, pos0 = pack0 & 0xffff;
        const int e1 = pack1 >> 16, pos1 = pack1 & 0xffff;

        __nv_bfloat16* dh0 = g_xhi + ((size_t)e0 * CAP + pos0) * Dm;
        __nv_bfloat16* dl0 = g_xlo + ((size_t)e0 * CAP + pos0) * Dm;
        __nv_bfloat16* dh1 = g_xhi + ((size_t)e1 * CAP + pos1) * Dm;
        __nv_bfloat16* dl1 = g_xlo + ((size_t)e1 * CAP + pos1) * Dm;
#pragma unroll
        for (int i = 0; i < 4; i++) {
            float f[4] = {xv[s][i].x, xv[s][i].y, xv[s][i].z, xv[s][i].w};
            alignas(8) __nv_bfloat16 h[4], l[4];
#pragma unroll
            for (int j = 0; j < 4; j++) {
                __nv_bfloat16 hh = __float2bfloat16_rn(f[j]);
                h[j] = hh;
                l[j] = __float2bfloat16_rn(f[j] - __bfloat162float(hh));
            }
            int eo = (i * 32 + lane) * 4;
            *(uint2*)(dh0 + eo) = *(uint2*)h;
            *(uint2*)(dl0 + eo) = *(uint2*)l;
            *(uint2*)(dh1 + eo) = *(uint2*)h;
            *(uint2*)(dl1 + eo) = *(uint2*)l;
        }
    }
}

// ---------------- GEMM mainloop: 512 thr, CTA 256x128, 4 buffers, 2 tiles/barrier ----------------
// Warp-staggered kk order: same-SMSP warps (same warpN, different warpM) start 1 chunk apart.
extern __shared__ char smx[];

#define STAGE_J(gj, bufi)                                                             \
    do {                                                                              \
        const int seg_ = (gj) >> SEG_SHIFT, kt_ = (gj) & SEG_MASK;                    \
        uint32_t sb2_ = smb + (bufi) * 49152;                                         \
        stage_tile256(sb2_,         Aseg[seg_] + aoff + kt_ * 64, STRIDE, tid);       \
        stage_tile128(sb2_ + 32768, Bseg[seg_] + boff + kt_ * 64, STRIDE, tid);       \
        CP_COMMIT();                                                                  \
    } while (0)

#define COMPUTE_TILE(bufidx)                                                          \
    do {                                                                              \
        uint32_t sa_ = smb + (bufidx) * 49152, sbb_ = sa_ + 32768;                    \
        _Pragma("unroll")                                                             \
        for (int kk16 = 0; kk16 < 4; kk16++) {                                        \
            const int kidx = (kk16 + warpM) & 3;                                      \
            uint32_t af[4][4];                                                        \
            _Pragma("unroll")                                                         \
            for (int mi = 0; mi < 4; mi++) {                                          \
                uint32_t off = (uint32_t)((warpM * 64 + mi * 16 + lr) * 128           \
                                          + (kidx * 2 + lc) * 16);                    \
                ldm_x4(af[mi], sa_ + swz(off));                                       \
            }                                                                         \
            uint32_t bfr[2][4];                                                       \
            _Pragma("unroll")                                                         \
            for (int nj = 0; nj < 2; nj++) {                                          \
                uint32_t off = (uint32_t)((warpN * 32 + nj * 16 + lr) * 128           \
                                          + (kidx * 2 + lc) * 16);                    \
                ldm_x4(bfr[nj], sbb_ + swz(off));                                     \
            }                                                                         \
            _Pragma("unroll")                                                         \
            for (int mi = 0; mi < 4; mi++)                                            \
                _Pragma("unroll")                                                     \
                for (int ni = 0; ni < 4; ni++) {                                      \
                    const int nj = ni >> 1, sub = ni & 1;                             \
                    mma16816(acc[mi][ni], af[mi], bfr[nj][sub], bfr[nj][sub + 2]);    \
                }                                                                     \
        }                                                                             \
    } while (0)

#define GEMM_MAINLOOP(NT, SEG_SHIFT_V, SEG_MASK_V, STRIDE_V, JOFF)                    \
    enum { SEG_SHIFT = SEG_SHIFT_V, SEG_MASK = SEG_MASK_V, STRIDE = STRIDE_V };       \
    uint32_t smb = smem_u32(smx);                                                     \
    STAGE_J((JOFF) + 0, 0);                                                           \
    STAGE_J((JOFF) + 1, 1);                                                           \
    float acc[4][4][4];                                                               \
    _Pragma("unroll") for (int a1 = 0; a1 < 4; a1++)                                  \
    _Pragma("unroll") for (int a2 = 0; a2 < 4; a2++)                                  \
    _Pragma("unroll") for (int a3 = 0; a3 < 4; a3++) acc[a1][a2][a3] = 0.f;           \
    const int lr = lane & 15, lc = lane >> 4;                                         \
    for (int i = 0; i < NT; i += 2) {                                                 \
        CP_WAIT(0);                                                                   \
        __syncthreads();                                                              \
        if (i + 2 < NT) STAGE_J((JOFF) + i + 2, (i + 2) & 3);                         \
        COMPUTE_TILE(i & 3);                                                          \
        if (i + 2 < NT) STAGE_J((JOFF) + i + 3, (i + 3) & 3);                         \
        COMPUTE_TILE((i + 1) & 3);                                                    \
    }

// ---------------- fc1: h = gelu(X @ W1^T), CTA 256 x 128 ----------------
__global__ __launch_bounds__(512) void fc1_kernel() {
    const int e = blockIdx.z;
    const int cnt = g_count[e];
    const int rowbase = blockIdx.y * 256;
    if (rowbase >= cnt) return;
    const int nbase = blockIdx.x * 128;

    const int tid = threadIdx.x;
    const int wid = tid >> 5, lane = tid & 31;
    const int warpM = wid >> 2, warpN = wid & 3;

    const __nv_bfloat16* Aseg[3] = {g_xhi, g_xhi, g_xlo};
    const __nv_bfloat16* Bseg[3] = {g_w1hi, g_w1lo, g_w1hi};
    const size_t aoff = ((size_t)e * CAP + rowbase) * Dm;
    const size_t boff = ((size_t)e * Hm + nbase) * Dm;

    GEMM_MAINLOOP(24, 3, 7, Dm, 0)

    const int r0 = lane >> 2, c0 = (lane & 3) * 2;
#pragma unroll
    for (int mi = 0; mi < 4; mi++) {
#pragma unroll
        for (int half = 0; half < 2; half++) {
            int row = rowbase + warpM * 64 + mi * 16 + r0 + half * 8;
            size_t rg = ((size_t)e * CAP + row) * Hm + nbase + warpN * 32 + c0;
#pragma unroll
            for (int ni = 0; ni < 4; ni++) {
                float v0 = acc[mi][ni][half * 2 + 0];
                float v1 = acc[mi][ni][half * 2 + 1];
                float gg0 = 0.5f * v0 * (1.0f + erff(v0 * 0.70710678118654752f));
                float gg1 = 0.5f * v1 * (1.0f + erff(v1 * 0.70710678118654752f));
                __nv_bfloat16 h0 = __float2bfloat16_rn(gg0);
                __nv_bfloat16 h1 = __float2bfloat16_rn(gg1);
                __nv_bfloat16 l0 = __float2bfloat16_rn(gg0 - __bfloat162float(h0));
                __nv_bfloat16 l1 = __float2bfloat16_rn(gg1 - __bfloat162float(h1));
                uint32_t hp = (uint32_t)*(uint16_t*)&h0 | ((uint32_t)*(uint16_t*)&h1 << 16);
                uint32_t lp = (uint32_t)*(uint16_t*)&l0 | ((uint32_t)*(uint16_t*)&l1 << 16);
                *(uint32_t*)(g_hhi + rg + ni * 8) = hp;
                *(uint32_t*)(g_hlo + rg + ni * 8) = lp;
            }
        }
    }
}

// ---------------- fc2: out[tok] += w * (H @ W2^T), split-K x2 ----------------
__global__ __launch_bounds__(512) void fc2_kernel(float* __restrict__ out) {
    const int e = blockIdx.z;
    const int cnt = g_count[e];
    const int rowbase = blockIdx.y * 256;
    if (rowbase >= cnt) return;
    const int ksplit = blockIdx.x >> 2;
    const int nbase = (blockIdx.x & 3) * 128;

    const int tid = threadIdx.x;
    const int wid = tid >> 5, lane = tid & 31;
    const int warpM = wid >> 2, warpN = wid & 3;

    const __nv_bfloat16* Aseg[3] = {g_hhi, g_hhi, g_hlo};
    const __nv_bfloat16* Bseg[3] = {g_w2hi, g_w2lo, g_w2hi};
    const size_t aoff = ((size_t)e * CAP + rowbase) * Hm;
    const size_t boff = ((size_t)e * Dm + nbase) * Hm;

    GEMM_MAINLOOP(24, 4, 15, Hm, ksplit * 24)

    const int r0 = lane >> 2, c0 = (lane & 3) * 2;
#pragma unroll
    for (int mi = 0; mi < 4; mi++) {
#pragma unroll
        for (int half = 0; half < 2; half++) {
            int pos = rowbase + warpM * 64 + mi * 16 + r0 + half * 8;
            if (pos >= cnt) continue;
            int entry = g_list[e * CAP + pos];
            float w = g_wt[entry];
            int tok = entry >> 1;
            float* op = out + (size_t)tok * Dm + nbase + warpN * 32 + c0;
#pragma unroll
            for (int ni = 0; ni < 4; ni++) {
                atomicAdd(op + ni * 8,     w * acc[mi][ni][half * 2 + 0]);
                atomicAdd(op + ni * 8 + 1, w * acc[mi][ni][half * 2 + 1]);
            }
        }
    }
}

// ---------------- launch ----------------
extern "C" void kernel_launch(void* const* d_in, const int* in_sizes, int n_in,
                              void* d_out, int out_size) {
    const float* x  = (const float*)d_in[0];
    const float* wr = (const float*)d_in[1];
    const float* br = (const float*)d_in[2];
    const float* w1 = (const float*)d_in[3];
    const float* w2 = (const float*)d_in[4];
    float* out = (float*)d_out;
    float* logits = out + (size_t)T_TOK * Dm;

    static void* count_ptr = nullptr;
    static int attr_done = 0;
    if (!attr_done) {
        cudaFuncSetAttribute(fc1_kernel, cudaFuncAttributeMaxDynamicSharedMemorySize, 196608);
        cudaFuncSetAttribute(fc2_kernel, cudaFuncAttributeMaxDynamicSharedMemorySize, 196608);
        cudaGetSymbolAddress(&count_ptr, g_count);
        attr_done = 1;
    }

    cudaMemsetAsync(count_ptr, 0, Em * sizeof(int));
    cudaMemsetAsync(out, 0, (size_t)T_TOK * Dm * sizeof(float));
    prep_router_kernel<<<2176, 256>>>(x, wr, br, w1, w2, logits);        // 1
    dim3 g1(Hm / 128, CAP / 256, Em);
    fc1_kernel<<<g1, 512, 196608>>>();                                   // 2
    dim3 g2((Dm / 128) * 2, CAP / 256, Em);
    fc2_kernel<<<g2, 512, 196608>>>(out);                                // 3
}